// round 5
// baseline (speedup 1.0000x reference)
#include <cuda_runtime.h>
#include <cuda_bf16.h>
#include <cstdint>
#include <math.h>

#define EXPERTS 8
#define HID     2048
#define INTER   1408
#define TOK     16384
#define I2      (2*INTER)

#define BM   128
#define BK   32
#define SST  40                       // smem row stride in bf16 (32 data + 8 pad) -> conflict-free
#define TN1  22                       // INTER/64 gate-col tiles
#define TN2  16                       // HID/128 out-col tiles
#define STAGE_ELEMS (2*128*SST)       // A(128x40) + B(128x40) = 10240 bf16
#define B_OFF (128*SST)               // 5120
#define SMEM_BYTES (2*STAGE_ELEMS*2)  // 40960 bytes, 2 stages

// ---- scratch (alloc-free rule: __device__ globals) ----
__device__ __nv_bfloat16 g_xb[(size_t)TOK * HID];            //  64 MB
__device__ __nv_bfloat16 g_w1[(size_t)EXPERTS * I2 * HID];   //  88 MB
__device__ __nv_bfloat16 g_w2[(size_t)EXPERTS * HID * INTER];//  44 MB
__device__ __nv_bfloat16 g_h [(size_t)TOK * INTER];          //  44 MB

// ---- helpers ----
__device__ __forceinline__ void cp16(void* dst_smem, const void* src_gmem, int sz) {
    unsigned s = (unsigned)__cvta_generic_to_shared(dst_smem);
    asm volatile("cp.async.cg.shared.global [%0], [%1], 16, %2;\n"
                 :: "r"(s), "l"(src_gmem), "r"(sz));
}
#define CP_COMMIT() asm volatile("cp.async.commit_group;\n")
#define CP_WAIT(n)  asm volatile("cp.async.wait_group %0;\n" :: "n"(n))

#define MMA(d, a, b) \
    asm volatile("mma.sync.aligned.m16n8k16.row.col.f32.bf16.bf16.f32 " \
        "{%0,%1,%2,%3},{%4,%5,%6,%7},{%8,%9},{%0,%1,%2,%3};\n" \
        : "+f"((d)[0]), "+f"((d)[1]), "+f"((d)[2]), "+f"((d)[3]) \
        : "r"((a)[0]), "r"((a)[1]), "r"((a)[2]), "r"((a)[3]), \
          "r"((b)[0]), "r"((b)[1]))

__device__ __forceinline__ float bround(float x) {
    return __bfloat162float(__float2bfloat16(x));
}

// Warp-tile compute on one 128x128x32 smem stage.
__device__ __forceinline__ void mma_tile(const __nv_bfloat16* As, const __nv_bfloat16* Bs,
                                         float acc[4][4][4], int wm, int wn, int g, int t) {
    #pragma unroll
    for (int kk = 0; kk < 2; ++kk) {
        uint32_t a[4][4], b[4][2];
        const int kb = kk*16 + t*2;
        #pragma unroll
        for (int im = 0; im < 4; ++im) {
            const __nv_bfloat16* p = As + (size_t)(wm*64 + im*16 + g)*SST + kb;
            a[im][0] = *(const uint32_t*)(p);
            a[im][1] = *(const uint32_t*)(p + 8*SST);
            a[im][2] = *(const uint32_t*)(p + 8);
            a[im][3] = *(const uint32_t*)(p + 8*SST + 8);
        }
        #pragma unroll
        for (int in = 0; in < 4; ++in) {
            const __nv_bfloat16* p = Bs + (size_t)(wn*32 + in*8 + g)*SST + kb;
            b[in][0] = *(const uint32_t*)(p);
            b[in][1] = *(const uint32_t*)(p + 8);
        }
        #pragma unroll
        for (int im = 0; im < 4; ++im)
            #pragma unroll
            for (int in = 0; in < 4; ++in)
                MMA(acc[im][in], a[im], b[in]);
    }
}

// ---- fp32 -> bf16 conversion ----
__global__ void cvt_kernel(const float4* __restrict__ src, __nv_bfloat162* __restrict__ dst, int n4) {
    int i = blockIdx.x * blockDim.x + threadIdx.x;
    if (i >= n4) return;
    float4 v = src[i];
    dst[2*i]   = __floats2bfloat162_rn(v.x, v.y);
    dst[2*i+1] = __floats2bfloat162_rn(v.z, v.w);
}

// ---- GEMM1: h = silu(x@Wg^T) * (x@Wu^T), fused ----
// Numerics: gate,up = bf16(f32-accum GEMM); silu computed STEPWISE in bf16
// (every elementwise HLO op rounds): e=bf16(exp(-g)); den=bf16(1+e);
// r=bf16(1/den); silu=bf16(g*r); h=bf16(silu*u).
__global__ __launch_bounds__(256) void gemm1_kernel(const int* __restrict__ counts) {
    extern __shared__ __nv_bfloat16 smem[];
    const int tid = threadIdx.x;

    // locate (expert, m-tile, n-tile) from linear block id
    int rem = blockIdx.x;
    int e = -1, off = 0, cnt = 0, tmi = 0, tni = 0;
    #pragma unroll
    for (int ee = 0; ee < EXPERTS; ++ee) {
        int c = counts[ee];
        int tm = (c + BM - 1) >> 7;
        int tiles = tm * TN1;
        if (e < 0) {
            if (rem < tiles) { e = ee; cnt = c; tmi = rem / TN1; tni = rem % TN1; }
            else             { rem -= tiles; off += c; }
        }
    }
    if (e < 0) return;
    const int m0 = tmi * BM;
    const int n0 = tni * 64;

    const __nv_bfloat16* Ag = g_xb + (size_t)off * HID;
    const __nv_bfloat16* Bg = g_w1 + (size_t)e * I2 * HID;

    const int warp = tid >> 5, lane = tid & 31;
    const int wm = warp >> 2, wn = warp & 3;
    const int g = lane >> 2, t = lane & 3;

    float acc[4][4][4];
    #pragma unroll
    for (int i = 0; i < 4; ++i)
        #pragma unroll
        for (int j = 0; j < 4; ++j)
            #pragma unroll
            for (int k = 0; k < 4; ++k) acc[i][j][k] = 0.f;

    auto issue = [&](int kt, int s) {
        __nv_bfloat16* base = smem + s * STAGE_ELEMS;
        #pragma unroll
        for (int i = 0; i < 2; ++i) {          // A tile: 512 x 16B chunks
            int id = tid + i*256;
            int row = id >> 2, kc = id & 3;
            int gm = m0 + row;
            int sz = (gm < cnt) ? 16 : 0;
            int gmc = (gm < cnt) ? gm : 0;
            cp16(base + row*SST + kc*8, Ag + (size_t)gmc*HID + kt*BK + kc*8, sz);
        }
        #pragma unroll
        for (int i = 0; i < 2; ++i) {          // B tile: rows 0-63 gate, 64-127 up
            int id = tid + i*256;
            int row = id >> 2, kc = id & 3;
            int gn = (row < 64) ? (n0 + row) : (INTER + n0 + row - 64);
            cp16(base + B_OFF + row*SST + kc*8, Bg + (size_t)gn*HID + kt*BK + kc*8, 16);
        }
    };

    const int KT = HID / BK;  // 64
    issue(0, 0); CP_COMMIT();
    for (int kt = 0; kt < KT; ++kt) {
        int s = kt & 1;
        if (kt + 1 < KT) { issue(kt + 1, s ^ 1); CP_COMMIT(); CP_WAIT(1); }
        else             { CP_WAIT(0); }
        __syncthreads();
        const __nv_bfloat16* As = smem + s * STAGE_ELEMS;
        mma_tile(As, As + B_OFF, acc, wm, wn, g, t);
        __syncthreads();
    }

    // ---- epilogue: exchange bf16 C tile (gate & up rounded here), stepwise-bf16 silu ----
    __nv_bfloat16* Cs = smem;   // 128 x 136 bf16 = 34816 B <= 40960
    #pragma unroll
    for (int im = 0; im < 4; ++im) {
        #pragma unroll
        for (int in = 0; in < 4; ++in) {
            int row = wm*64 + im*16 + g;
            int col = wn*32 + in*8 + t*2;
            *(__nv_bfloat162*)(Cs + (size_t)row*136 + col) =
                __floats2bfloat162_rn(acc[im][in][0], acc[im][in][1]);
            *(__nv_bfloat162*)(Cs + (size_t)(row+8)*136 + col) =
                __floats2bfloat162_rn(acc[im][in][2], acc[im][in][3]);
        }
    }
    __syncthreads();

    const int row = tid >> 1;
    const int cbase = (tid & 1) * 32;
    if (m0 + row < cnt) {
        __nv_bfloat16* dst = g_h + (size_t)(off + m0 + row) * INTER + n0 + cbase;
        const __nv_bfloat16* crow = Cs + (size_t)row * 136;
        #pragma unroll
        for (int j = 0; j < 32; j += 2) {
            __nv_bfloat162 gg = *(const __nv_bfloat162*)(crow + cbase + j);
            __nv_bfloat162 uu = *(const __nv_bfloat162*)(crow + 64 + cbase + j);
            float g0 = __bfloat162float(gg.x), g1 = __bfloat162float(gg.y);
            float u0 = __bfloat162float(uu.x), u1 = __bfloat162float(uu.y);
            // stepwise bf16 elementwise chain (each HLO op rounds to bf16):
            float e0   = bround(expf(-g0));
            float e1   = bround(expf(-g1));
            float den0 = bround(1.f + e0);
            float den1 = bround(1.f + e1);
            float r0   = bround(1.f / den0);
            float r1   = bround(1.f / den1);
            float s0   = bround(g0 * r0);       // silu(gate)
            float s1   = bround(g1 * r1);
            *(__nv_bfloat162*)(dst + j) = __floats2bfloat162_rn(s0 * u0, s1 * u1); // h round
        }
    }
}

// ---- GEMM2: out = f32(bf16(h @ down^T)) ----
__global__ __launch_bounds__(256) void gemm2_kernel(const int* __restrict__ counts,
                                                    float* __restrict__ out) {
    extern __shared__ __nv_bfloat16 smem[];
    const int tid = threadIdx.x;

    int rem = blockIdx.x;
    int e = -1, off = 0, cnt = 0, tmi = 0, tni = 0;
    #pragma unroll
    for (int ee = 0; ee < EXPERTS; ++ee) {
        int c = counts[ee];
        int tm = (c + BM - 1) >> 7;
        int tiles = tm * TN2;
        if (e < 0) {
            if (rem < tiles) { e = ee; cnt = c; tmi = rem / TN2; tni = rem % TN2; }
            else             { rem -= tiles; off += c; }
        }
    }
    if (e < 0) return;
    const int m0 = tmi * BM;
    const int n0 = tni * 128;

    const __nv_bfloat16* Ag = g_h  + (size_t)off * INTER;
    const __nv_bfloat16* Bg = g_w2 + (size_t)e * HID * INTER;

    const int warp = tid >> 5, lane = tid & 31;
    const int wm = warp >> 2, wn = warp & 3;
    const int g = lane >> 2, t = lane & 3;

    float acc[4][4][4];
    #pragma unroll
    for (int i = 0; i < 4; ++i)
        #pragma unroll
        for (int j = 0; j < 4; ++j)
            #pragma unroll
            for (int k = 0; k < 4; ++k) acc[i][j][k] = 0.f;

    auto issue = [&](int kt, int s) {
        __nv_bfloat16* base = smem + s * STAGE_ELEMS;
        #pragma unroll
        for (int i = 0; i < 2; ++i) {
            int id = tid + i*256;
            int row = id >> 2, kc = id & 3;
            int gm = m0 + row;
            int sz = (gm < cnt) ? 16 : 0;
            int gmc = (gm < cnt) ? gm : 0;
            cp16(base + row*SST + kc*8, Ag + (size_t)gmc*INTER + kt*BK + kc*8, sz);
        }
        #pragma unroll
        for (int i = 0; i < 2; ++i) {
            int id = tid + i*256;
            int row = id >> 2, kc = id & 3;
            int gn = n0 + row;
            cp16(base + B_OFF + row*SST + kc*8, Bg + (size_t)gn*INTER + kt*BK + kc*8, 16);
        }
    };

    const int KT = INTER / BK;  // 44
    issue(0, 0); CP_COMMIT();
    for (int kt = 0; kt < KT; ++kt) {
        int s = kt & 1;
        if (kt + 1 < KT) { issue(kt + 1, s ^ 1); CP_COMMIT(); CP_WAIT(1); }
        else             { CP_WAIT(0); }
        __syncthreads();
        const __nv_bfloat16* As = smem + s * STAGE_ELEMS;
        mma_tile(As, As + B_OFF, acc, wm, wn, g, t);
        __syncthreads();
    }

    // epilogue: ragged_dot output dtype bf16 -> round, then exact upcast to f32
    #pragma unroll
    for (int im = 0; im < 4; ++im) {
        #pragma unroll
        for (int in = 0; in < 4; ++in) {
            int lm  = wm*64 + im*16 + g;
            int col = n0 + wn*32 + in*8 + t*2;
            if (m0 + lm < cnt) {
                float2* p = (float2*)(out + (size_t)(off + m0 + lm)*HID + col);
                *p = make_float2(bround(acc[im][in][0]), bround(acc[im][in][1]));
            }
            if (m0 + lm + 8 < cnt) {
                float2* p = (float2*)(out + (size_t)(off + m0 + lm + 8)*HID + col);
                *p = make_float2(bround(acc[im][in][2]), bround(acc[im][in][3]));
            }
        }
    }
}

extern "C" void kernel_launch(void* const* d_in, const int* in_sizes, int n_in,
                              void* d_out, int out_size) {
    const float* x      = (const float*)d_in[0];
    const float* w1     = (const float*)d_in[1];
    const float* w2     = (const float*)d_in[2];
    const int*   counts = (const int*)d_in[3];
    float*       out    = (float*)d_out;

    void *pxb, *pw1, *pw2;
    cudaGetSymbolAddress(&pxb, g_xb);
    cudaGetSymbolAddress(&pw1, g_w1);
    cudaGetSymbolAddress(&pw2, g_w2);

    const int n4x  = (TOK * HID) / 4;
    const int n4w1 = (EXPERTS * I2 * HID) / 4;
    const int n4w2 = (EXPERTS * HID * INTER) / 4;
    cvt_kernel<<<(n4x  + 255) / 256, 256>>>((const float4*)x,  (__nv_bfloat162*)pxb, n4x);
    cvt_kernel<<<(n4w1 + 255) / 256, 256>>>((const float4*)w1, (__nv_bfloat162*)pw1, n4w1);
    cvt_kernel<<<(n4w2 + 255) / 256, 256>>>((const float4*)w2, (__nv_bfloat162*)pw2, n4w2);

    const int maxtm = TOK / BM + EXPERTS;  // worst-case m-tiles across experts
    gemm1_kernel<<<maxtm * TN1, 256, SMEM_BYTES>>>(counts);
    gemm2_kernel<<<maxtm * TN2, 256, SMEM_BYTES>>>(counts, out);
}

// round 7
// speedup vs baseline: 1.1783x; 1.1783x over previous
#include <cuda_runtime.h>
#include <cuda_bf16.h>
#include <cstdint>
#include <math.h>

#define EXPERTS 8
#define HID     2048
#define INTER   1408
#define TOK     16384
#define I2      (2*INTER)

#define BM   128
#define BK   32
#define SST  40                        // smem row stride in bf16 (32 data + 8 pad)
#define SSTB 80                        // row stride in bytes
#define TN1  22                        // INTER/64 gate-col tiles
#define TN2  16                        // HID/128 out-col tiles
#define TILE_BYTES (128*SSTB)          // 10240 B per tile
#define B_OFFB TILE_BYTES
#define STAGE_BYTES (2*TILE_BYTES)     // A + B = 20480 B
#define NSTAGE 4
#define SMEM_BYTES (NSTAGE*STAGE_BYTES)  // 81920 B

// ---- scratch (alloc-free rule: __device__ globals) ----
__device__ __nv_bfloat16 g_xb[(size_t)TOK * HID];
__device__ __nv_bfloat16 g_w1[(size_t)EXPERTS * I2 * HID];
__device__ __nv_bfloat16 g_w2[(size_t)EXPERTS * HID * INTER];
__device__ __nv_bfloat16 g_h [(size_t)TOK * INTER];

// ---- helpers ----
__device__ __forceinline__ uint32_t smem_u32(const void* p) {
    uint32_t a;
    asm("{ .reg .u64 t; cvta.to.shared.u64 t, %1; cvt.u32.u64 %0, t; }" : "=r"(a) : "l"(p));
    return a;
}
__device__ __forceinline__ void cp16(uint32_t dst_smem, const void* src, int sz) {
    asm volatile("cp.async.cg.shared.global [%0], [%1], 16, %2;\n"
                 :: "r"(dst_smem), "l"(src), "r"(sz));
}
#define CP_COMMIT() asm volatile("cp.async.commit_group;\n")
#define CP_WAIT(n)  asm volatile("cp.async.wait_group %0;\n" :: "n"(n))

#define LDSM4(r, addr) \
    asm volatile("ldmatrix.sync.aligned.m8n8.x4.shared.b16 {%0,%1,%2,%3}, [%4];" \
        : "=r"((r)[0]), "=r"((r)[1]), "=r"((r)[2]), "=r"((r)[3]) : "r"(addr))

#define MMA(d, a, b) \
    asm volatile("mma.sync.aligned.m16n8k16.row.col.f32.bf16.bf16.f32 " \
        "{%0,%1,%2,%3},{%4,%5,%6,%7},{%8,%9},{%0,%1,%2,%3};\n" \
        : "+f"((d)[0]), "+f"((d)[1]), "+f"((d)[2]), "+f"((d)[3]) \
        : "r"((a)[0]), "r"((a)[1]), "r"((a)[2]), "r"((a)[3]), \
          "r"((b)[0]), "r"((b)[1]))

__device__ __forceinline__ float bround(float x) {
    return __bfloat162float(__float2bfloat16(x));
}

// Warp-tile compute on one 128x128x32 stage via ldmatrix fragments.
// aBase/bBase are lane-resolved shared addresses into this stage.
__device__ __forceinline__ void mma_tile(uint32_t aBase, uint32_t bBase, float acc[4][4][4]) {
    #pragma unroll
    for (int kk = 0; kk < 2; ++kk) {
        uint32_t a[4][4], b[2][4];
        #pragma unroll
        for (int im = 0; im < 4; ++im)
            LDSM4(a[im], aBase + im*(16*SSTB) + kk*32);
        #pragma unroll
        for (int p = 0; p < 2; ++p)
            LDSM4(b[p], bBase + p*(16*SSTB) + kk*32);
        #pragma unroll
        for (int im = 0; im < 4; ++im) {
            MMA(acc[im][0], a[im], (&b[0][0]));
            MMA(acc[im][1], a[im], (&b[0][2]));
            MMA(acc[im][2], a[im], (&b[1][0]));
            MMA(acc[im][3], a[im], (&b[1][2]));
        }
    }
}

// ---- fp32 -> bf16 conversion ----
__global__ void cvt_kernel(const float4* __restrict__ src, __nv_bfloat162* __restrict__ dst, int n4) {
    int i = blockIdx.x * blockDim.x + threadIdx.x;
    if (i >= n4) return;
    float4 v = src[i];
    dst[2*i]   = __floats2bfloat162_rn(v.x, v.y);
    dst[2*i+1] = __floats2bfloat162_rn(v.z, v.w);
}

// ---- GEMM1: h = silu(x@Wg^T) * (x@Wu^T), fused ----
__global__ __launch_bounds__(256, 2) void gemm1_kernel(const int* __restrict__ counts) {
    extern __shared__ char dsm[];
    const int tid = threadIdx.x;

    int rem = blockIdx.x;
    int e = -1, off = 0, cnt = 0, tmi = 0, tni = 0;
    #pragma unroll
    for (int ee = 0; ee < EXPERTS; ++ee) {
        int c = counts[ee];
        int tm = (c + BM - 1) >> 7;
        int tiles = tm * TN1;
        if (e < 0) {
            if (rem < tiles) { e = ee; cnt = c; tmi = rem / TN1; tni = rem % TN1; }
            else             { rem -= tiles; off += c; }
        }
    }
    if (e < 0) return;
    const int m0 = tmi * BM;
    const int n0 = tni * 64;

    const __nv_bfloat16* Ag = g_xb + (size_t)off * HID;
    const __nv_bfloat16* Bg = g_w1 + (size_t)e * I2 * HID;

    const int warp = tid >> 5, lane = tid & 31;
    const int wm = warp >> 2, wn = warp & 3;
    const int g = lane >> 2, t = lane & 3;

    const uint32_t sb = smem_u32(dsm);
    const uint32_t aLane = (uint32_t)(wm*64 + (lane & 15))*SSTB + (lane >> 4)*16;
    const uint32_t bLane = B_OFFB + (uint32_t)(wn*32 + (lane >> 4)*8 + (lane & 7))*SSTB
                           + ((lane >> 3) & 1)*16;

    float acc[4][4][4];
    #pragma unroll
    for (int i = 0; i < 4; ++i)
        #pragma unroll
        for (int j = 0; j < 4; ++j)
            #pragma unroll
            for (int k = 0; k < 4; ++k) acc[i][j][k] = 0.f;

    auto issue = [&](int kt, int s) {
        const uint32_t base = sb + s * STAGE_BYTES;
        #pragma unroll
        for (int i = 0; i < 2; ++i) {          // A tile: 512 x 16B chunks
            int id = tid + i*256;
            int row = id >> 2, kc = id & 3;
            int gm = m0 + row;
            int sz = (gm < cnt) ? 16 : 0;
            int gmc = (gm < cnt) ? gm : 0;
            cp16(base + row*SSTB + kc*16, Ag + (size_t)gmc*HID + kt*BK + kc*8, sz);
        }
        #pragma unroll
        for (int i = 0; i < 2; ++i) {          // B tile: rows 0-63 gate, 64-127 up
            int id = tid + i*256;
            int row = id >> 2, kc = id & 3;
            int gn = (row < 64) ? (n0 + row) : (INTER + n0 + row - 64);
            cp16(base + B_OFFB + row*SSTB + kc*16, Bg + (size_t)gn*HID + kt*BK + kc*8, 16);
        }
    };

    const int KT = HID / BK;  // 64
    issue(0, 0); CP_COMMIT();
    issue(1, 1); CP_COMMIT();
    issue(2, 2); CP_COMMIT();
    for (int kt = 0; kt < KT; ++kt) {
        const int s = kt & 3;
        CP_WAIT(2);
        __syncthreads();
        if (kt + 3 < KT) issue(kt + 3, (kt + 3) & 3);
        CP_COMMIT();
        const uint32_t stg = sb + s * STAGE_BYTES;
        mma_tile(stg + aLane, stg + bLane, acc);
    }
    __syncthreads();

    // ---- epilogue: exchange bf16 C tile, stepwise-bf16 silu (validated numerics) ----
    __nv_bfloat16* Cs = (__nv_bfloat16*)dsm;   // 128 x 136 bf16 = 34816 B
    #pragma unroll
    for (int im = 0; im < 4; ++im) {
        #pragma unroll
        for (int in = 0; in < 4; ++in) {
            int row = wm*64 + im*16 + g;
            int col = wn*32 + in*8 + t*2;
            *(__nv_bfloat162*)(Cs + (size_t)row*136 + col) =
                __floats2bfloat162_rn(acc[im][in][0], acc[im][in][1]);
            *(__nv_bfloat162*)(Cs + (size_t)(row+8)*136 + col) =
                __floats2bfloat162_rn(acc[im][in][2], acc[im][in][3]);
        }
    }
    __syncthreads();

    const int row = tid >> 1;
    const int cbase = (tid & 1) * 32;
    if (m0 + row < cnt) {
        __nv_bfloat16* dst = g_h + (size_t)(off + m0 + row) * INTER + n0 + cbase;
        const __nv_bfloat16* crow = Cs + (size_t)row * 136;
        #pragma unroll
        for (int j = 0; j < 32; j += 2) {
            __nv_bfloat162 gg = *(const __nv_bfloat162*)(crow + cbase + j);
            __nv_bfloat162 uu = *(const __nv_bfloat162*)(crow + 64 + cbase + j);
            float g0 = __bfloat162float(gg.x), g1 = __bfloat162float(gg.y);
            float u0 = __bfloat162float(uu.x), u1 = __bfloat162float(uu.y);
            float e0   = bround(expf(-g0));
            float e1   = bround(expf(-g1));
            float den0 = bround(1.f + e0);
            float den1 = bround(1.f + e1);
            float r0   = bround(1.f / den0);
            float r1   = bround(1.f / den1);
            float s0   = bround(g0 * r0);
            float s1   = bround(g1 * r1);
            *(__nv_bfloat162*)(dst + j) = __floats2bfloat162_rn(s0 * u0, s1 * u1);
        }
    }
}

// ---- GEMM2: out = f32(bf16(h @ down^T)) ----
__global__ __launch_bounds__(256, 2) void gemm2_kernel(const int* __restrict__ counts,
                                                       float* __restrict__ out) {
    extern __shared__ char dsm[];
    const int tid = threadIdx.x;

    int rem = blockIdx.x;
    int e = -1, off = 0, cnt = 0, tmi = 0, tni = 0;
    #pragma unroll
    for (int ee = 0; ee < EXPERTS; ++ee) {
        int c = counts[ee];
        int tm = (c + BM - 1) >> 7;
        int tiles = tm * TN2;
        if (e < 0) {
            if (rem < tiles) { e = ee; cnt = c; tmi = rem / TN2; tni = rem % TN2; }
            else             { rem -= tiles; off += c; }
        }
    }
    if (e < 0) return;
    const int m0 = tmi * BM;
    const int n0 = tni * 128;

    const __nv_bfloat16* Ag = g_h  + (size_t)off * INTER;
    const __nv_bfloat16* Bg = g_w2 + (size_t)e * HID * INTER;

    const int warp = tid >> 5, lane = tid & 31;
    const int wm = warp >> 2, wn = warp & 3;
    const int g = lane >> 2, t = lane & 3;

    const uint32_t sb = smem_u32(dsm);
    const uint32_t aLane = (uint32_t)(wm*64 + (lane & 15))*SSTB + (lane >> 4)*16;
    const uint32_t bLane = B_OFFB + (uint32_t)(wn*32 + (lane >> 4)*8 + (lane & 7))*SSTB
                           + ((lane >> 3) & 1)*16;

    float acc[4][4][4];
    #pragma unroll
    for (int i = 0; i < 4; ++i)
        #pragma unroll
        for (int j = 0; j < 4; ++j)
            #pragma unroll
            for (int k = 0; k < 4; ++k) acc[i][j][k] = 0.f;

    auto issue = [&](int kt, int s) {
        const uint32_t base = sb + s * STAGE_BYTES;
        #pragma unroll
        for (int i = 0; i < 2; ++i) {
            int id = tid + i*256;
            int row = id >> 2, kc = id & 3;
            int gm = m0 + row;
            int sz = (gm < cnt) ? 16 : 0;
            int gmc = (gm < cnt) ? gm : 0;
            cp16(base + row*SSTB + kc*16, Ag + (size_t)gmc*INTER + kt*BK + kc*8, sz);
        }
        #pragma unroll
        for (int i = 0; i < 2; ++i) {
            int id = tid + i*256;
            int row = id >> 2, kc = id & 3;
            int gn = n0 + row;
            cp16(base + B_OFFB + row*SSTB + kc*16, Bg + (size_t)gn*INTER + kt*BK + kc*8, 16);
        }
    };

    const int KT = INTER / BK;  // 44
    issue(0, 0); CP_COMMIT();
    issue(1, 1); CP_COMMIT();
    issue(2, 2); CP_COMMIT();
    for (int kt = 0; kt < KT; ++kt) {
        const int s = kt & 3;
        CP_WAIT(2);
        __syncthreads();
        if (kt + 3 < KT) issue(kt + 3, (kt + 3) & 3);
        CP_COMMIT();
        const uint32_t stg = sb + s * STAGE_BYTES;
        mma_tile(stg + aLane, stg + bLane, acc);
    }

    // epilogue: round to bf16 then exact f32 upcast (validated numerics)
    #pragma unroll
    for (int im = 0; im < 4; ++im) {
        #pragma unroll
        for (int in = 0; in < 4; ++in) {
            int lm  = wm*64 + im*16 + g;
            int col = n0 + wn*32 + in*8 + t*2;
            if (m0 + lm < cnt) {
                float2* p = (float2*)(out + (size_t)(off + m0 + lm)*HID + col);
                *p = make_float2(bround(acc[im][in][0]), bround(acc[im][in][1]));
            }
            if (m0 + lm + 8 < cnt) {
                float2* p = (float2*)(out + (size_t)(off + m0 + lm + 8)*HID + col);
                *p = make_float2(bround(acc[im][in][2]), bround(acc[im][in][3]));
            }
        }
    }
}

extern "C" void kernel_launch(void* const* d_in, const int* in_sizes, int n_in,
                              void* d_out, int out_size) {
    const float* x      = (const float*)d_in[0];
    const float* w1     = (const float*)d_in[1];
    const float* w2     = (const float*)d_in[2];
    const int*   counts = (const int*)d_in[3];
    float*       out    = (float*)d_out;

    void *pxb, *pw1, *pw2;
    cudaGetSymbolAddress(&pxb, g_xb);
    cudaGetSymbolAddress(&pw1, g_w1);
    cudaGetSymbolAddress(&pw2, g_w2);

    cudaFuncSetAttribute(gemm1_kernel, cudaFuncAttributeMaxDynamicSharedMemorySize, SMEM_BYTES);
    cudaFuncSetAttribute(gemm2_kernel, cudaFuncAttributeMaxDynamicSharedMemorySize, SMEM_BYTES);

    const int n4x  = (TOK * HID) / 4;
    const int n4w1 = (EXPERTS * I2 * HID) / 4;
    const int n4w2 = (EXPERTS * HID * INTER) / 4;
    cvt_kernel<<<(n4x  + 255) / 256, 256>>>((const float4*)x,  (__nv_bfloat162*)pxb, n4x);
    cvt_kernel<<<(n4w1 + 255) / 256, 256>>>((const float4*)w1, (__nv_bfloat162*)pw1, n4w1);
    cvt_kernel<<<(n4w2 + 255) / 256, 256>>>((const float4*)w2, (__nv_bfloat162*)pw2, n4w2);

    const int maxtm = TOK / BM + EXPERTS;
    gemm1_kernel<<<maxtm * TN1, 256, SMEM_BYTES>>>(counts);
    gemm2_kernel<<<maxtm * TN2, 256, SMEM_BYTES>>>(counts, out);
}